// round 5
// baseline (speedup 1.0000x reference)
#include <cuda_runtime.h>

// ---------------- problem constants ----------------
#define NPART   65536
#define DDIM    8
#define HID     64
#define WIDTH   128
#define TT      8
#define NSUB    4
#define NSEG    7
#define NSLOT   63            // 7 segments * 9 time slots
#define SLOT_F  4612          // 4 header floats + 128 rows * 36 floats
#define SLOT_F4 1153          // SLOT_F / 4
#define POUT    3200          // 3*WIDTH*DDIM + WIDTH
#define ZT_ELEMS (TT*NPART*DDIM)

// Coefficient slots: per slot: [0..1]=(-Csum,-Csum), [2..3]=pad,
// then per row i (36 floats): W dup x8 (16), U' dup x8 (16), (B,B,c,c) (4).
__device__ __align__(16) float g_slots[(size_t)NSLOT * SLOT_F];

typedef unsigned long long u64;

// ---------------- f32x2 helpers ----------------
__device__ __forceinline__ u64 pk(float x, float y) {
    u64 r; asm("mov.b64 %0, {%1, %2};" : "=l"(r) : "f"(x), "f"(y)); return r;
}
__device__ __forceinline__ void upk(float& x, float& y, u64 v) {
    asm("mov.b64 {%0, %1}, %2;" : "=f"(x), "=f"(y) : "l"(v));
}
__device__ __forceinline__ u64 f2(u64 a, u64 b, u64 c) {
    u64 d; asm("fma.rn.f32x2 %0, %1, %2, %3;" : "=l"(d) : "l"(a), "l"(b), "l"(c)); return d;
}
__device__ __forceinline__ u64 m2(u64 a, u64 b) {
    u64 d; asm("mul.rn.f32x2 %0, %1, %2;" : "=l"(d) : "l"(a), "l"(b)); return d;
}
__device__ __forceinline__ u64 a2(u64 a, u64 b) {
    u64 d; asm("add.rn.f32x2 %0, %1, %2;" : "=l"(d) : "l"(a), "l"(b)); return d;
}
__device__ __forceinline__ float tnh(float x) {
    float r; asm("tanh.approx.f32 %0, %1;" : "=f"(r) : "f"(x)); return r;
}
__device__ __forceinline__ void lds2(u64& a, u64& b, unsigned addr) {
    asm volatile("ld.shared.v2.b64 {%0, %1}, [%2];" : "=l"(a), "=l"(b) : "r"(addr));
}
__device__ __forceinline__ u64 lds1(unsigned addr) {
    u64 a; asm volatile("ld.shared.b64 %0, [%1];" : "=l"(a) : "r"(addr)); return a;
}

// ---------------- hypernet precompute: 63 slots ----------------
__global__ void hyper_kernel(const float* __restrict__ ts,
                             const float* __restrict__ w1, const float* __restrict__ b1,
                             const float* __restrict__ w2, const float* __restrict__ b2,
                             const float* __restrict__ w3, const float* __restrict__ b3)
{
    __shared__ float h1s[HID];
    __shared__ float h2s[HID];
    __shared__ float ps[POUT];
    __shared__ float csh[WIDTH];

    int s = blockIdx.x;
    int j = s / 9, m = s % 9;
    float t0 = ts[j], t1 = ts[j + 1];
    float t = t0 + (float)m * (t1 - t0) * 0.125f;   // t0 + m*dt/2, dt=(t1-t0)/4
    int tid = threadIdx.x;                           // 128 threads

    if (tid < HID) h1s[tid] = tanhf(w1[tid] * t + b1[tid]);
    __syncthreads();
    if (tid < HID) {
        float acc = b2[tid];
        const float* wr = w2 + tid * HID;
        #pragma unroll 8
        for (int k = 0; k < HID; k++) acc = fmaf(wr[k], h1s[k], acc);
        h2s[tid] = tanhf(acc);
    }
    __syncthreads();
    for (int o = tid; o < POUT; o += 128) {
        float acc = b3[o];
        const float4* wr = (const float4*)(w3 + (size_t)o * HID);
        #pragma unroll
        for (int k = 0; k < HID / 4; k++) {
            float4 v = wr[k];
            acc = fmaf(v.x, h2s[4 * k + 0], acc);
            acc = fmaf(v.y, h2s[4 * k + 1], acc);
            acc = fmaf(v.z, h2s[4 * k + 2], acc);
            acc = fmaf(v.w, h2s[4 * k + 3], acc);
        }
        ps[o] = acc;
    }
    __syncthreads();

    float* slot = g_slots + (size_t)s * SLOT_F;
    {
        int i = tid;                                 // 128 rows, one per thread
        float c = 0.f;
        float* row = slot + 4 + i * 36;
        float B = ps[3 * WIDTH * DDIM + i];
        #pragma unroll
        for (int d = 0; d < DDIM; d++) {
            float w = ps[i * 8 + d];
            float u = ps[1024 + i * 8 + d];
            float g = ps[2048 + i * 8 + d];
            float sg = 1.f / (1.f + expf(-g));
            u = u * sg * (1.0f / (float)WIDTH);      // pre-scale U by 1/WIDTH
            row[2 * d + 0] = w;  row[2 * d + 1] = w;
            row[16 + 2 * d + 0] = u;  row[16 + 2 * d + 1] = u;
            c = fmaf(w, u, c);                       // c already includes 1/WIDTH
        }
        row[32] = B; row[33] = B; row[34] = c; row[35] = c;
        csh[i] = c;
    }
    __syncthreads();
    if (tid == 0) {
        float cs = 0.f;
        for (int i = 0; i < WIDTH; i++) cs += csh[i];
        slot[0] = -cs; slot[1] = -cs; slot[2] = 0.f; slot[3] = 0.f;  // -Csum
    }
}

// ---------------- RHS eval: pair of particles packed f32x2 ----------------
__device__ __forceinline__ void rhs_eval(unsigned sb, const u64 zs[8], u64 dz[8], u64& dl)
{
    u64 S = 0ull;
    #pragma unroll
    for (int d = 0; d < 8; d++) dz[d] = 0ull;
    unsigned a = sb + 16;
    #pragma unroll 4
    for (int i = 0; i < WIDTH; i++) {
        u64 q0, q1, q2, q3, q4, q5, q6, q7, Bd, Cd;
        lds2(Bd, Cd, a + 128);
        lds2(q0, q1, a);      lds2(q2, q3, a + 16);
        lds2(q4, q5, a + 32); lds2(q6, q7, a + 48);
        u64 e = f2(q0, zs[0], Bd);
        u64 o = m2(q1, zs[1]);
        e = f2(q2, zs[2], e);  o = f2(q3, zs[3], o);
        e = f2(q4, zs[4], e);  o = f2(q5, zs[5], o);
        e = f2(q6, zs[6], e);  o = f2(q7, zs[7], o);
        u64 pre = a2(e, o);
        float px, py; upk(px, py, pre);
        u64 h = pk(tnh(px), tnh(py));
        u64 hh = m2(h, h);
        S = f2(hh, Cd, S);                     // S = sum h^2 * c
        lds2(q0, q1, a + 64);  lds2(q2, q3, a + 80);
        lds2(q4, q5, a + 96);  lds2(q6, q7, a + 112);
        dz[0] = f2(h, q0, dz[0]);  dz[1] = f2(h, q1, dz[1]);
        dz[2] = f2(h, q2, dz[2]);  dz[3] = f2(h, q3, dz[3]);
        dz[4] = f2(h, q4, dz[4]);  dz[5] = f2(h, q5, dz[5]);
        dz[6] = f2(h, q6, dz[6]);  dz[7] = f2(h, q7, dz[7]);
        a += 144;
    }
    u64 nCs = lds1(sb);                        // (-Csum, -Csum)
    dl = a2(S, nCs);                           // dlogp/dt = S - Csum = -trace
}

__device__ __forceinline__ void stage_slot(float4* s4, const float4* g4, int tid)
{
    __syncthreads();
    #pragma unroll
    for (int k = 0; k < 9; k++) s4[tid + k * 128] = g4[tid + k * 128];
    if (tid == 0) s4[1152] = g4[1152];
    __syncthreads();
}

// ---------------- main integration kernel ----------------
__global__ void __launch_bounds__(128) cnf_main(const float* __restrict__ ts,
                                                const float* __restrict__ z0,
                                                const float* __restrict__ lp0,
                                                float* __restrict__ out)
{
    __shared__ __align__(16) float sco[SLOT_F];
    unsigned sb = (unsigned)__cvta_generic_to_shared(sco);
    float4* s4 = (float4*)sco;
    int tid = threadIdx.x;
    int P = blockIdx.x * 128 + tid;            // pair index
    int p0 = 2 * P, p1 = p0 + 1;

    const float4* zr0 = (const float4*)(z0 + (size_t)p0 * 8);
    const float4* zr1 = (const float4*)(z0 + (size_t)p1 * 8);
    float4 a0 = zr0[0], a1 = zr0[1], c0 = zr1[0], c1 = zr1[1];
    u64 zz[8];
    zz[0] = pk(a0.x, c0.x); zz[1] = pk(a0.y, c0.y);
    zz[2] = pk(a0.z, c0.z); zz[3] = pk(a0.w, c0.w);
    zz[4] = pk(a1.x, c1.x); zz[5] = pk(a1.y, c1.y);
    zz[6] = pk(a1.z, c1.z); zz[7] = pk(a1.w, c1.w);
    float l0 = lp0[p0], l1 = lp0[p1];
    u64 ll = pk(l0, l1);

    // t = ts[0] outputs (copies of inputs)
    {
        float4* o0 = (float4*)(out + (size_t)p0 * 8);
        o0[0] = a0; o0[1] = a1;
        float4* o1 = (float4*)(out + (size_t)p1 * 8);
        o1[0] = c0; o1[1] = c1;
        out[ZT_ELEMS + p0] = l0;
        out[ZT_ELEMS + p1] = l1;
    }

    const u64 two = pk(2.f, 2.f);
    int staged = -1;
    u64 zs[8], dz[8], acc[8], dl, lacc;

    #pragma unroll 1
    for (int j = 0; j < NSEG; j++) {
        float t0 = ts[j];
        float dt = (ts[j + 1] - t0) * 0.25f;
        u64 dt2 = pk(dt * 0.5f, dt * 0.5f);
        u64 dtf = pk(dt, dt);
        u64 dt6 = pk(dt * (1.f / 6.f), dt * (1.f / 6.f));

        #pragma unroll 1
        for (int s = 0; s < NSUB; s++) {
            int base = j * 9 + 2 * s;
            if (staged != base)
                stage_slot(s4, (const float4*)(g_slots + (size_t)base * SLOT_F), tid);

            // k1
            rhs_eval(sb, zz, dz, dl);
            #pragma unroll
            for (int d = 0; d < 8; d++) { acc[d] = dz[d]; zs[d] = f2(dt2, dz[d], zz[d]); }
            lacc = dl;

            // k2 (t + dt/2)
            stage_slot(s4, (const float4*)(g_slots + (size_t)(base + 1) * SLOT_F), tid);
            rhs_eval(sb, zs, dz, dl);
            #pragma unroll
            for (int d = 0; d < 8; d++) { acc[d] = f2(two, dz[d], acc[d]); zs[d] = f2(dt2, dz[d], zz[d]); }
            lacc = f2(two, dl, lacc);

            // k3 (same slot, no restage)
            rhs_eval(sb, zs, dz, dl);
            #pragma unroll
            for (int d = 0; d < 8; d++) { acc[d] = f2(two, dz[d], acc[d]); zs[d] = f2(dtf, dz[d], zz[d]); }
            lacc = f2(two, dl, lacc);

            // k4 (t + dt)
            stage_slot(s4, (const float4*)(g_slots + (size_t)(base + 2) * SLOT_F), tid);
            rhs_eval(sb, zs, dz, dl);
            #pragma unroll
            for (int d = 0; d < 8; d++) { acc[d] = a2(acc[d], dz[d]); zz[d] = f2(dt6, acc[d], zz[d]); }
            lacc = a2(lacc, dl);
            ll = f2(dt6, lacc, ll);

            staged = base + 2;
        }

        // write outputs at time index j+1
        float zx[8], zy[8];
        #pragma unroll
        for (int d = 0; d < 8; d++) upk(zx[d], zy[d], zz[d]);
        size_t ob = (size_t)(j + 1) * NPART;
        float4* w0p = (float4*)(out + (ob + p0) * 8);
        w0p[0] = make_float4(zx[0], zx[1], zx[2], zx[3]);
        w0p[1] = make_float4(zx[4], zx[5], zx[6], zx[7]);
        float4* w1p = (float4*)(out + (ob + p1) * 8);
        w1p[0] = make_float4(zy[0], zy[1], zy[2], zy[3]);
        w1p[1] = make_float4(zy[4], zy[5], zy[6], zy[7]);
        float lx, lyv; upk(lx, lyv, ll);
        out[ZT_ELEMS + ob + p0] = lx;
        out[ZT_ELEMS + ob + p1] = lyv;
    }
}

// ---------------- launch ----------------
extern "C" void kernel_launch(void* const* d_in, const int* in_sizes, int n_in,
                              void* d_out, int out_size)
{
    const float* ts  = (const float*)d_in[0];
    const float* z0  = (const float*)d_in[1];
    const float* lp0 = (const float*)d_in[2];
    const float* w1  = (const float*)d_in[3];
    const float* b1  = (const float*)d_in[4];
    const float* w2  = (const float*)d_in[5];
    const float* b2  = (const float*)d_in[6];
    const float* w3  = (const float*)d_in[7];
    const float* b3  = (const float*)d_in[8];
    float* out = (float*)d_out;

    hyper_kernel<<<NSLOT, 128>>>(ts, w1, b1, w2, b2, w3, b3);
    cnf_main<<<NPART / 256, 128>>>(ts, z0, lp0, out);
    (void)in_sizes; (void)n_in; (void)out_size;
}